// round 16
// baseline (speedup 1.0000x reference)
#include <cuda_runtime.h>
#include <cuda_fp16.h>
#include <math.h>
#include <stdint.h>

#define NMAX 1000000
#define BMAX 16384

__device__ float g_t[BMAX * 64];        // t = u @ W1b + b1           [B,64]
__device__ float g_e[NMAX];             // exp(score) per node        [N]
__device__ float g_num[BMAX * 128];     // segmented sum e*x          [B,128]
__device__ float g_den[BMAX];           // segmented sum e            [B]
__device__ float g_x2[BMAX * 256];      // concat(u, pooled)          [B,256]
__device__ float g_h2[BMAX * 256];      // relu(x2@Wg1+bg1)           [B,256]

// ================= helpers =================
__device__ __forceinline__ uint32_t smem_u32(const void* p) {
    uint32_t a;
    asm("{ .reg .u64 t; cvta.to.shared.u64 t, %1; cvt.u32.u64 %0, t; }" : "=r"(a) : "l"(p));
    return a;
}

__device__ __forceinline__ void ldmat4(uint32_t* r, uint32_t addr) {
    asm volatile("ldmatrix.sync.aligned.m8n8.x4.shared.b16 {%0,%1,%2,%3}, [%4];"
        : "=r"(r[0]), "=r"(r[1]), "=r"(r[2]), "=r"(r[3]) : "r"(addr));
}

// fp16 HMMA, fp32 accumulate
__device__ __forceinline__ void hmma(float* c, const uint32_t* a, uint32_t b0, uint32_t b1) {
    asm volatile(
        "mma.sync.aligned.m16n8k16.row.col.f32.f16.f16.f32 "
        "{%0,%1,%2,%3}, {%4,%5,%6,%7}, {%8,%9}, {%0,%1,%2,%3};"
        : "+f"(c[0]), "+f"(c[1]), "+f"(c[2]), "+f"(c[3])
        : "r"(a[0]), "r"(a[1]), "r"(a[2]), "r"(a[3]), "r"(b0), "r"(b1));
}

// split one float4 to fp16 hi/lo packed pairs
__device__ __forceinline__ void split4h(float4 v, uint2& hp, uint2& lp) {
    __half2 h01 = __floats2half2_rn(v.x, v.y);
    __half2 h23 = __floats2half2_rn(v.z, v.w);
    float2 f01 = __half22float2(h01);
    float2 f23 = __half22float2(h23);
    __half2 l01 = __floats2half2_rn(v.x - f01.x, v.y - f01.y);
    __half2 l23 = __floats2half2_rn(v.z - f23.x, v.w - f23.y);
    hp = make_uint2(*(uint32_t*)&h01, *(uint32_t*)&h23);
    lp = make_uint2(*(uint32_t*)&l01, *(uint32_t*)&l23);
}

// ================= zero accumulators =================
__global__ void zero_kernel(int B) {
    int i = blockIdx.x * blockDim.x + threadIdx.x;
    int total = B * 128 + B;
    if (i < B * 128) g_num[i] = 0.f;
    else if (i < total) g_den[i - B * 128] = 0.f;
}

// ================= shared tile geometry =================
#define A_STRIDE   272
#define A_TILE_B   (128 * A_STRIDE)           // 34816 (128-row tile, gemms)

// B-fragment layout: [kc][lane(80B stride)][nt(8B)] -> 4x LDS.128, conflict-free
#define BKC_STRIDE 2560                       // 32 lanes * 80 B

#define GB_AH 0
#define GB_AL A_TILE_B
#define GB_B  (2 * A_TILE_B)                  // 69632; K<=256 -> 16*2560 = 40960
#define GB_TOTAL (GB_B + 40960)               // 110592

// ---- shared pieces for the GEMM family (single fp16 B operand) ----
__device__ __forceinline__ void gemm_pack_B(
    char* smem, const float* __restrict__ Bw, int Nn, int K, int nBase, int tid)
{
    int nEnt = (K >> 4) * 256;
    for (int i = tid; i < nEnt; i += 256) {
        int li = i & 31, nt = (i >> 5) & 7, kcc = i >> 8;
        int n = nBase + nt * 8 + (li >> 2);
        int k0 = kcc * 16 + 2 * (li & 3);
        __half2 b0 = __floats2half2_rn(Bw[(size_t)k0 * Nn + n],       Bw[(size_t)(k0 + 1) * Nn + n]);
        __half2 b1 = __floats2half2_rn(Bw[(size_t)(k0 + 8) * Nn + n], Bw[(size_t)(k0 + 9) * Nn + n]);
        *(uint2*)(smem + GB_B + kcc * BKC_STRIDE + li * 80 + nt * 8)
            = make_uint2(*(uint32_t*)&b0, *(uint32_t*)&b1);
    }
}

__device__ __forceinline__ void gemm_mma_chunk(
    char* smem, uint32_t sbase, float acc[8][4], int wid, int lane,
    int lrow, int lk, int kcBase)
{
    uint32_t aH = sbase + GB_AH + (wid * 16 + lrow) * A_STRIDE + lk;
    uint32_t aL = aH + A_TILE_B;
#pragma unroll
    for (int kcc = 0; kcc < 8; kcc++) {
        uint32_t ah[4], al[4];
        ldmat4(ah, aH + kcc * 32);
        ldmat4(al, aL + kcc * 32);
        const uint4* bp = (const uint4*)(smem + GB_B + (kcBase + kcc) * BKC_STRIDE + lane * 80);
        uint4 q0 = bp[0], q1 = bp[1], q2 = bp[2], q3 = bp[3];
        hmma(acc[0], ah, q0.x, q0.y); hmma(acc[0], al, q0.x, q0.y);
        hmma(acc[1], ah, q0.z, q0.w); hmma(acc[1], al, q0.z, q0.w);
        hmma(acc[2], ah, q1.x, q1.y); hmma(acc[2], al, q1.x, q1.y);
        hmma(acc[3], ah, q1.z, q1.w); hmma(acc[3], al, q1.z, q1.w);
        hmma(acc[4], ah, q2.x, q2.y); hmma(acc[4], al, q2.x, q2.y);
        hmma(acc[5], ah, q2.z, q2.w); hmma(acc[5], al, q2.z, q2.w);
        hmma(acc[6], ah, q3.x, q3.y); hmma(acc[6], al, q3.x, q3.y);
        hmma(acc[7], ah, q3.z, q3.w); hmma(acc[7], al, q3.z, q3.w);
    }
}

__device__ __forceinline__ void gemm_epilogue(
    float acc[8][4], const float* __restrict__ bias, float* __restrict__ C,
    int Nn, int relu, int mBase, int nBase, int wid, int g, int t)
{
    int row0 = mBase + wid * 16 + g;
    int row1 = row0 + 8;
#pragma unroll
    for (int nt = 0; nt < 8; nt++) {
        int col = nBase + nt * 8 + 2 * t;
        float2 bv = *(const float2*)(bias + col);
        float v00 = acc[nt][0] + bv.x, v01 = acc[nt][1] + bv.y;
        float v10 = acc[nt][2] + bv.x, v11 = acc[nt][3] + bv.y;
        if (relu) {
            v00 = fmaxf(v00, 0.f); v01 = fmaxf(v01, 0.f);
            v10 = fmaxf(v10, 0.f); v11 = fmaxf(v11, 0.f);
        }
        *(float2*)(C + (size_t)row0 * Nn + col) = make_float2(v00, v01);
        *(float2*)(C + (size_t)row1 * Nn + col) = make_float2(v10, v11);
    }
}

// ================= generic fp16-split HMMA GEMM =================
__global__ void __launch_bounds__(256) hmma_gemm(
    const float* __restrict__ A, const float* __restrict__ Bw,
    const float* __restrict__ bias, float* __restrict__ C,
    int M, int Nn, int K, int relu)
{
    extern __shared__ __align__(1024) char smem[];
    uint32_t sbase = smem_u32(smem);
    int tid = threadIdx.x, wid = tid >> 5, lane = tid & 31;
    int g = lane >> 2, t = lane & 3;
    int mBase = blockIdx.y * 128, nBase = blockIdx.x * 64;
    int lrow = lane & 15, lk = (lane >> 4) * 16;

    gemm_pack_B(smem, Bw, Nn, K, nBase, tid);

    float acc[8][4];
#pragma unroll
    for (int nt = 0; nt < 8; nt++)
#pragma unroll
        for (int c = 0; c < 4; c++) acc[nt][c] = 0.f;

    for (int kb = 0; kb < K; kb += 128) {
        for (int i = tid; i < 128 * 32; i += 256) {
            int m = i >> 5, c4 = i & 31;
            float4 v = *(const float4*)(A + (size_t)(mBase + m) * K + kb + c4 * 4);
            uint2 hp, lp; split4h(v, hp, lp);
            uint32_t off = m * A_STRIDE + c4 * 8;
            *(uint2*)(smem + GB_AH + off) = hp;
            *(uint2*)(smem + GB_AL + off) = lp;
        }
        __syncthreads();
        gemm_mma_chunk(smem, sbase, acc, wid, lane, lrow, lk, kb >> 4);
        __syncthreads();
    }
    gemm_epilogue(acc, bias, C, Nn, relu, mBase, nBase, wid, g, t);
}

// ================= fused scores + softmax-pool kernel =================
// 64-row tiles, 128 threads, fp16 2-term split, packed-B LDS.128, 4 CTAs/SM.
#define A64_TILE_B (64 * A_STRIDE)            // 17408
#define SC_AH 0
#define SC_AL A64_TILE_B                      // 17408
#define SC_B  (2 * A64_TILE_B)                // 34816; 8*2560 = 20480
#define SC_GB (SC_B + 20480)                  // 55296 (64 ints)
#define SC_TOTAL (SC_GB + 256)                // 55552

__global__ void __launch_bounds__(128, 4) scores_pool_kernel(
    const float* __restrict__ x, const int* __restrict__ batch,
    const float* __restrict__ W1, const float* __restrict__ W2,
    const float* __restrict__ b2, int N)
{
    extern __shared__ __align__(1024) char smem[];
    uint32_t sbase = smem_u32(smem);
    int*   gb = (int*)(smem + SC_GB);
    int tid = threadIdx.x, wid = tid >> 5, lane = tid & 31;
    int g = lane >> 2, t = lane & 3;
    int lrow = lane & 15, lk = (lane >> 4) * 16;

    // pre-pack B = W1a^T fragments (single fp16, packed layout)
    for (int i = tid; i < 2048; i += 128) {
        int li = i & 31, nt = (i >> 5) & 7, kc = i >> 8;
        int n = nt * 8 + (li >> 2);
        int k0 = kc * 16 + 2 * (li & 3);
        __half2 b0 = __floats2half2_rn(W1[k0 * 64 + n],       W1[(k0 + 1) * 64 + n]);
        __half2 b1 = __floats2half2_rn(W1[(k0 + 8) * 64 + n], W1[(k0 + 9) * 64 + n]);
        *(uint2*)(smem + SC_B + kc * BKC_STRIDE + li * 80 + nt * 8)
            = make_uint2(*(uint32_t*)&b0, *(uint32_t*)&b1);
    }

    float2 w2r[8];
#pragma unroll
    for (int nt = 0; nt < 8; nt++)
        w2r[nt] = *(const float2*)(W2 + nt * 8 + 2 * t);
    float b2v = b2[0];

    int T = (N + 63) >> 6;
    int G = gridDim.x;
    int L = ((int)blockIdx.x < T) ? (T - (int)blockIdx.x + G - 1) / G : 0;

    __syncthreads();

    int mRow = tid >> 5;           // 0..3; rows stride 4
    int c4   = tid & 31;

    for (int j = 0; j < L; j++) {
        long base = ((long)blockIdx.x + (long)j * G) * 64;

        // ---- stage tile (64 rows): LDG -> fp16 hi/lo -> STS; batch ids ----
#pragma unroll
        for (int r = 0; r < 16; r++) {
            int m = mRow + r * 4;
            long gi = base + m;
            float4 v = make_float4(0.f, 0.f, 0.f, 0.f);
            if (gi < N) v = __ldg((const float4*)(x + gi * 128 + c4 * 4));
            uint2 hp, lp; split4h(v, hp, lp);
            uint32_t off = m * A_STRIDE + c4 * 8;
            *(uint2*)(smem + SC_AH + off) = hp;
            *(uint2*)(smem + SC_AL + off) = lp;
        }
        if (tid < 64) {
            long gi = base + tid;
            gb[tid] = (gi < N) ? batch[gi] : 0;
        }
        __syncthreads();

        // ---- HMMA: each warp 16 rows, packed-B LDS.128 ----
        uint32_t aH = sbase + SC_AH + (wid * 16 + lrow) * A_STRIDE + lk;
        uint32_t aL = aH + A64_TILE_B;
        float acc[8][4];
#pragma unroll
        for (int nt = 0; nt < 8; nt++)
#pragma unroll
            for (int c = 0; c < 4; c++) acc[nt][c] = 0.f;

#pragma unroll
        for (int kc = 0; kc < 8; kc++) {
            uint32_t ah[4], al[4];
            ldmat4(ah, aH + kc * 32);
            ldmat4(al, aL + kc * 32);
            const uint4* bp = (const uint4*)(smem + SC_B + kc * BKC_STRIDE + lane * 80);
            uint4 q0 = bp[0], q1 = bp[1], q2 = bp[2], q3 = bp[3];
            hmma(acc[0], ah, q0.x, q0.y); hmma(acc[0], al, q0.x, q0.y);
            hmma(acc[1], ah, q0.z, q0.w); hmma(acc[1], al, q0.z, q0.w);
            hmma(acc[2], ah, q1.x, q1.y); hmma(acc[2], al, q1.x, q1.y);
            hmma(acc[3], ah, q1.z, q1.w); hmma(acc[3], al, q1.z, q1.w);
            hmma(acc[4], ah, q2.x, q2.y); hmma(acc[4], al, q2.x, q2.y);
            hmma(acc[5], ah, q2.z, q2.w); hmma(acc[5], al, q2.z, q2.w);
            hmma(acc[6], ah, q3.x, q3.y); hmma(acc[6], al, q3.x, q3.y);
            hmma(acc[7], ah, q3.z, q3.w); hmma(acc[7], al, q3.z, q3.w);
        }

        // ---- epilogue: e = exp(s); g_e, RED den; per-warp pooling ----
        int m0 = wid * 16 + g;
        int m1 = m0 + 8;
        long r0 = base + m0, r1 = base + m1;
        int bi0 = gb[m0], bi1 = gb[m1];
        {
            const float* t0 = g_t + (size_t)bi0 * 64;
            const float* t1 = g_t + (size_t)bi1 * 64;
            float s0 = 0.f, s1 = 0.f;
#pragma unroll
            for (int nt = 0; nt < 8; nt++) {
                int col = nt * 8 + 2 * t;
                float2 tv0 = *(const float2*)(t0 + col);
                float2 tv1 = *(const float2*)(t1 + col);
                float2 w = w2r[nt];
                s0 += fmaxf(acc[nt][0] + tv0.x, 0.f) * w.x
                    + fmaxf(acc[nt][1] + tv0.y, 0.f) * w.y;
                s1 += fmaxf(acc[nt][2] + tv1.x, 0.f) * w.x
                    + fmaxf(acc[nt][3] + tv1.y, 0.f) * w.y;
            }
            s0 += __shfl_xor_sync(0xffffffffu, s0, 1);
            s0 += __shfl_xor_sync(0xffffffffu, s0, 2);
            s1 += __shfl_xor_sync(0xffffffffu, s1, 1);
            s1 += __shfl_xor_sync(0xffffffffu, s1, 2);
            float e0 = (r0 < N) ? __expf(s0 + b2v) : 0.f;
            float e1 = (r1 < N) ? __expf(s1 + b2v) : 0.f;
            if (t == 0) {
                if (r0 < N) { g_e[r0] = e0; atomicAdd(g_den + bi0, e0); }
                if (r1 < N) { g_e[r1] = e1; atomicAdd(g_den + bi1, e1); }
            }

            // per-warp pooling: 16 rows x 4 feats/lane from smem (x ~ hi+lo)
            float a0 = 0.f, a1 = 0.f, a2 = 0.f, a3 = 0.f;
            int rowBase = wid * 16;
#pragma unroll
            for (int r = 0; r < 16; r++) {
                int row = rowBase + r;
                float er = (r < 8) ? __shfl_sync(0xffffffffu, e0, r * 4)
                                   : __shfl_sync(0xffffffffu, e1, (r - 8) * 4);
                uint2 h = *(uint2*)(smem + SC_AH + row * A_STRIDE + lane * 8);
                uint2 l = *(uint2*)(smem + SC_AL + row * A_STRIDE + lane * 8);
                float2 h0 = __half22float2(*(__half2*)&h.x);
                float2 h1 = __half22float2(*(__half2*)&h.y);
                float2 l0 = __half22float2(*(__half2*)&l.x);
                float2 l1 = __half22float2(*(__half2*)&l.y);
                a0 += er * (h0.x + l0.x);
                a1 += er * (h0.y + l0.y);
                a2 += er * (h1.x + l1.x);
                a3 += er * (h1.y + l1.y);
                int gcur = gb[row];
                if (r == 15 || gb[row + 1] != gcur) {
                    float* dst = g_num + (size_t)gcur * 128 + lane * 4;
                    atomicAdd(dst,     a0);
                    atomicAdd(dst + 1, a1);
                    atomicAdd(dst + 2, a2);
                    atomicAdd(dst + 3, a3);
                    a0 = a1 = a2 = a3 = 0.f;
                }
            }
        }
        __syncthreads();
    }
}

// ================= merged post-processing =================
__global__ void __launch_bounds__(256) post_kernel(
    const float* __restrict__ u, const int* __restrict__ batch,
    float* __restrict__ attn, int N, int B)
{
    int nX2 = B * 32;
    int stride = gridDim.x * blockDim.x;
    for (int i = blockIdx.x * blockDim.x + threadIdx.x; i < nX2; i += stride) {
        int g = i >> 5, q = i & 31;
        float den = g_den[g];
        float inv = (den > 0.f) ? 1.f / den : 0.f;
        float4 uv = *(const float4*)(u + (size_t)g * 128 + q * 4);
        float4 nv = *(const float4*)(g_num + (size_t)g * 128 + q * 4);
        nv.x *= inv; nv.y *= inv; nv.z *= inv; nv.w *= inv;
        *(float4*)(g_x2 + (size_t)g * 256 + q * 4)       = uv;
        *(float4*)(g_x2 + (size_t)g * 256 + 128 + q * 4) = nv;
    }
    for (int i = blockIdx.x * blockDim.x + threadIdx.x; i < N; i += stride) {
        attn[i] = g_e[i] / g_den[batch[i]];
    }
}

// ================= launch =================
extern "C" void kernel_launch(void* const* d_in, const int* in_sizes, int n_in,
                              void* d_out, int out_size)
{
    const float* x     = (const float*)d_in[0];
    const float* u     = (const float*)d_in[3];
    const int*   batch = (const int*)d_in[4];
    const float* W1    = (const float*)d_in[5];
    const float* b1    = (const float*)d_in[6];
    const float* W2    = (const float*)d_in[7];
    const float* b2    = (const float*)d_in[8];
    const float* Wg1   = (const float*)d_in[9];
    const float* bg1   = (const float*)d_in[10];
    const float* Wg2   = (const float*)d_in[11];
    const float* bg2   = (const float*)d_in[12];

    int N = in_sizes[0] / 128;
    int B = in_sizes[3] / 128;

    float* out  = (float*)d_out;
    float* attn = (float*)d_out + (size_t)B * 128;

    float *t_ptr, *x2_ptr, *h2_ptr;
    cudaGetSymbolAddress((void**)&t_ptr,  g_t);
    cudaGetSymbolAddress((void**)&x2_ptr, g_x2);
    cudaGetSymbolAddress((void**)&h2_ptr, g_h2);

    cudaFuncSetAttribute(hmma_gemm,
                         cudaFuncAttributeMaxDynamicSharedMemorySize, GB_TOTAL);
    cudaFuncSetAttribute(scores_pool_kernel,
                         cudaFuncAttributeMaxDynamicSharedMemorySize, SC_TOTAL);

    // 0) zero accumulators
    zero_kernel<<<(B * 129 + 255) / 256, 256>>>(B);

    // 1) t[B,64] = u @ W1b + b1
    {
        dim3 grid(1, B / 128);
        hmma_gemm<<<grid, 256, GB_TOTAL>>>(u, W1 + 128 * 64, b1, t_ptr, B, 64, 128, 0);
    }

    // 2) fused scores + softmax-pool (64-row tiles, fp16 2-term, 4 CTAs/SM)
    {
        int T = (N + 63) / 64;
        int grid = T < 592 ? T : 592;
        scores_pool_kernel<<<grid, 128, SC_TOTAL>>>(x, batch, W1, W2, b2, N);
    }

    // 3) merged post-processing (x2 build + attn)
    post_kernel<<<1184, 256>>>(u, batch, attn, N, B);

    // 4) global MLP via fp16-split HMMA
    {
        dim3 g3a(256 / 64, B / 128);
        hmma_gemm<<<g3a, 256, GB_TOTAL>>>(x2_ptr, Wg1, bg1, h2_ptr, B, 256, 256, 1);
        dim3 g3b(128 / 64, B / 128);
        hmma_gemm<<<g3b, 256, GB_TOTAL>>>(h2_ptr, Wg2, bg2, out, B, 128, 256, 0);
    }
}

// round 17
// speedup vs baseline: 1.0233x; 1.0233x over previous
#include <cuda_runtime.h>
#include <cuda_fp16.h>
#include <math.h>
#include <stdint.h>

#define NMAX 1000000
#define BMAX 16384

__device__ float g_t[BMAX * 64];        // t = u @ W1b + b1           [B,64]
__device__ float g_e[NMAX];             // exp(score) per node        [N]
__device__ float g_num[BMAX * 128];     // segmented sum e*x          [B,128]
__device__ float g_den[BMAX];           // segmented sum e            [B]
__device__ float g_x2[BMAX * 256];      // concat(u, pooled)          [B,256]
__device__ float g_h2[BMAX * 256];      // relu(x2@Wg1+bg1)           [B,256]

// packed fp16 weight fragments: per kc: 32 lanes x 80B (8 nt x uint2 + 16B pad)
// uint2 index = kc*320 + lane*10 + nt
__device__ uint4 g_pw1a[8  * 160];          // W1a   (K=128, 1 n-block)
__device__ uint4 g_pw1b[8  * 160];          // W1b   (K=128, 1 n-block)
__device__ uint4 g_pwg1[4 * 16 * 160];      // Wg1   (K=256, 4 n-blocks)
__device__ uint4 g_pwg2[2 * 16 * 160];      // Wg2   (K=256, 2 n-blocks)

// ================= helpers =================
__device__ __forceinline__ uint32_t smem_u32(const void* p) {
    uint32_t a;
    asm("{ .reg .u64 t; cvta.to.shared.u64 t, %1; cvt.u32.u64 %0, t; }" : "=r"(a) : "l"(p));
    return a;
}

__device__ __forceinline__ void ldmat4(uint32_t* r, uint32_t addr) {
    asm volatile("ldmatrix.sync.aligned.m8n8.x4.shared.b16 {%0,%1,%2,%3}, [%4];"
        : "=r"(r[0]), "=r"(r[1]), "=r"(r[2]), "=r"(r[3]) : "r"(addr));
}

// fp16 HMMA, fp32 accumulate
__device__ __forceinline__ void hmma(float* c, const uint32_t* a, uint32_t b0, uint32_t b1) {
    asm volatile(
        "mma.sync.aligned.m16n8k16.row.col.f32.f16.f16.f32 "
        "{%0,%1,%2,%3}, {%4,%5,%6,%7}, {%8,%9}, {%0,%1,%2,%3};"
        : "+f"(c[0]), "+f"(c[1]), "+f"(c[2]), "+f"(c[3])
        : "r"(a[0]), "r"(a[1]), "r"(a[2]), "r"(a[3]), "r"(b0), "r"(b1));
}

// split one float4 to fp16 hi/lo packed pairs
__device__ __forceinline__ void split4h(float4 v, uint2& hp, uint2& lp) {
    __half2 h01 = __floats2half2_rn(v.x, v.y);
    __half2 h23 = __floats2half2_rn(v.z, v.w);
    float2 f01 = __half22float2(h01);
    float2 f23 = __half22float2(h23);
    __half2 l01 = __floats2half2_rn(v.x - f01.x, v.y - f01.y);
    __half2 l23 = __floats2half2_rn(v.z - f23.x, v.w - f23.y);
    hp = make_uint2(*(uint32_t*)&h01, *(uint32_t*)&h23);
    lp = make_uint2(*(uint32_t*)&l01, *(uint32_t*)&l23);
}

// ================= weight prepack (once per launch) =================
__device__ __forceinline__ void pack_one(
    const float* __restrict__ Bw, int Nn, int nBase, int e, uint2* dst)
{
    int li = e & 31, nt = (e >> 5) & 7, kc = e >> 8;
    int n = nBase + nt * 8 + (li >> 2);
    int k0 = kc * 16 + 2 * (li & 3);
    __half2 b0 = __floats2half2_rn(Bw[(size_t)k0 * Nn + n],       Bw[(size_t)(k0 + 1) * Nn + n]);
    __half2 b1 = __floats2half2_rn(Bw[(size_t)(k0 + 8) * Nn + n], Bw[(size_t)(k0 + 9) * Nn + n]);
    dst[kc * 320 + li * 10 + nt] = make_uint2(*(uint32_t*)&b0, *(uint32_t*)&b1);
}

__global__ void pack_weights(
    const float* __restrict__ W1, const float* __restrict__ Wg1,
    const float* __restrict__ Wg2)
{
    int i = blockIdx.x * blockDim.x + threadIdx.x;
    if (i < 2048) {
        pack_one(W1, 64, 0, i, (uint2*)g_pw1a);
    } else if (i < 4096) {
        pack_one(W1 + 128 * 64, 64, 0, i - 2048, (uint2*)g_pw1b);
    } else if (i < 4096 + 16384) {
        int e = i - 4096;
        int nb = e / 4096, ei = e % 4096;
        pack_one(Wg1, 256, nb * 64, ei, (uint2*)(g_pwg1 + nb * 16 * 160));
    } else if (i < 4096 + 16384 + 8192) {
        int e = i - 4096 - 16384;
        int nb = e / 4096, ei = e % 4096;
        pack_one(Wg2, 128, nb * 64, ei, (uint2*)(g_pwg2 + nb * 16 * 160));
    }
}

// ================= zero accumulators =================
__global__ void zero_kernel(int B) {
    int i = blockIdx.x * blockDim.x + threadIdx.x;
    int total = B * 128 + B;
    if (i < B * 128) g_num[i] = 0.f;
    else if (i < total) g_den[i - B * 128] = 0.f;
}

// ================= shared tile geometry =================
#define A_STRIDE   272
#define A_TILE_B   (128 * A_STRIDE)           // 34816 (128-row tile, gemms)
#define BKC_STRIDE 2560                       // 32 lanes * 80 B

#define GB_AH 0
#define GB_AL A_TILE_B
#define GB_B  (2 * A_TILE_B)                  // 69632; K<=256 -> 16*2560 = 40960
#define GB_TOTAL (GB_B + 40960)               // 110592

__device__ __forceinline__ void gemm_mma_chunk(
    char* smem, uint32_t sbase, float acc[8][4], int wid, int lane,
    int lrow, int lk, int kcBase)
{
    uint32_t aH = sbase + GB_AH + (wid * 16 + lrow) * A_STRIDE + lk;
    uint32_t aL = aH + A_TILE_B;
#pragma unroll
    for (int kcc = 0; kcc < 8; kcc++) {
        uint32_t ah[4], al[4];
        ldmat4(ah, aH + kcc * 32);
        ldmat4(al, aL + kcc * 32);
        const uint4* bp = (const uint4*)(smem + GB_B + (kcBase + kcc) * BKC_STRIDE + lane * 80);
        uint4 q0 = bp[0], q1 = bp[1], q2 = bp[2], q3 = bp[3];
        hmma(acc[0], ah, q0.x, q0.y); hmma(acc[0], al, q0.x, q0.y);
        hmma(acc[1], ah, q0.z, q0.w); hmma(acc[1], al, q0.z, q0.w);
        hmma(acc[2], ah, q1.x, q1.y); hmma(acc[2], al, q1.x, q1.y);
        hmma(acc[3], ah, q1.z, q1.w); hmma(acc[3], al, q1.z, q1.w);
        hmma(acc[4], ah, q2.x, q2.y); hmma(acc[4], al, q2.x, q2.y);
        hmma(acc[5], ah, q2.z, q2.w); hmma(acc[5], al, q2.z, q2.w);
        hmma(acc[6], ah, q3.x, q3.y); hmma(acc[6], al, q3.x, q3.y);
        hmma(acc[7], ah, q3.z, q3.w); hmma(acc[7], al, q3.z, q3.w);
    }
}

__device__ __forceinline__ void gemm_epilogue(
    float acc[8][4], const float* __restrict__ bias, float* __restrict__ C,
    int Nn, int relu, int mBase, int nBase, int wid, int g, int t)
{
    int row0 = mBase + wid * 16 + g;
    int row1 = row0 + 8;
#pragma unroll
    for (int nt = 0; nt < 8; nt++) {
        int col = nBase + nt * 8 + 2 * t;
        float2 bv = *(const float2*)(bias + col);
        float v00 = acc[nt][0] + bv.x, v01 = acc[nt][1] + bv.y;
        float v10 = acc[nt][2] + bv.x, v11 = acc[nt][3] + bv.y;
        if (relu) {
            v00 = fmaxf(v00, 0.f); v01 = fmaxf(v01, 0.f);
            v10 = fmaxf(v10, 0.f); v11 = fmaxf(v11, 0.f);
        }
        *(float2*)(C + (size_t)row0 * Nn + col) = make_float2(v00, v01);
        *(float2*)(C + (size_t)row1 * Nn + col) = make_float2(v10, v11);
    }
}

// ================= generic fp16-split HMMA GEMM (prepacked B) =================
__global__ void __launch_bounds__(256) hmma_gemm(
    const float* __restrict__ A, const uint4* __restrict__ packedB,
    const float* __restrict__ bias, float* __restrict__ C,
    int M, int Nn, int K, int relu)
{
    extern __shared__ __align__(1024) char smem[];
    uint32_t sbase = smem_u32(smem);
    int tid = threadIdx.x, wid = tid >> 5, lane = tid & 31;
    int g = lane >> 2, t = lane & 3;
    int mBase = blockIdx.y * 128, nBase = blockIdx.x * 64;
    int lrow = lane & 15, lk = (lane >> 4) * 16;

    // coalesced copy of this n-block's packed B fragments
    int nU4 = (K >> 4) * 160;
    {
        const uint4* src = packedB + (size_t)blockIdx.x * nU4;
        uint4* dst = (uint4*)(smem + GB_B);
        for (int i = tid; i < nU4; i += 256) dst[i] = src[i];
    }

    float acc[8][4];
#pragma unroll
    for (int nt = 0; nt < 8; nt++)
#pragma unroll
        for (int c = 0; c < 4; c++) acc[nt][c] = 0.f;

    for (int kb = 0; kb < K; kb += 128) {
        for (int i = tid; i < 128 * 32; i += 256) {
            int m = i >> 5, c4 = i & 31;
            float4 v = *(const float4*)(A + (size_t)(mBase + m) * K + kb + c4 * 4);
            uint2 hp, lp; split4h(v, hp, lp);
            uint32_t off = m * A_STRIDE + c4 * 8;
            *(uint2*)(smem + GB_AH + off) = hp;
            *(uint2*)(smem + GB_AL + off) = lp;
        }
        __syncthreads();
        gemm_mma_chunk(smem, sbase, acc, wid, lane, lrow, lk, kb >> 4);
        __syncthreads();
    }
    gemm_epilogue(acc, bias, C, Nn, relu, mBase, nBase, wid, g, t);
}

// ================= fused scores + softmax-pool kernel =================
// 64-row tiles, 128 threads, fp16 2-term split, prepacked B, 4 CTAs/SM.
#define A64_TILE_B (64 * A_STRIDE)            // 17408
#define SC_AH 0
#define SC_AL A64_TILE_B                      // 17408
#define SC_B  (2 * A64_TILE_B)                // 34816; 8*2560 = 20480
#define SC_GB (SC_B + 20480)                  // 55296 (64 ints)
#define SC_TOTAL (SC_GB + 256)                // 55552

__global__ void __launch_bounds__(128, 4) scores_pool_kernel(
    const float* __restrict__ x, const int* __restrict__ batch,
    const float* __restrict__ W2, const float* __restrict__ b2, int N)
{
    extern __shared__ __align__(1024) char smem[];
    uint32_t sbase = smem_u32(smem);
    int*   gb = (int*)(smem + SC_GB);
    int tid = threadIdx.x, wid = tid >> 5, lane = tid & 31;
    int g = lane >> 2, t = lane & 3;
    int lrow = lane & 15, lk = (lane >> 4) * 16;

    // coalesced copy of prepacked W1a fragments (1280 uint4)
    {
        uint4* dst = (uint4*)(smem + SC_B);
        for (int i = tid; i < 1280; i += 128) dst[i] = g_pw1a[i];
    }

    float2 w2r[8];
#pragma unroll
    for (int nt = 0; nt < 8; nt++)
        w2r[nt] = *(const float2*)(W2 + nt * 8 + 2 * t);
    float b2v = b2[0];

    int T = (N + 63) >> 6;
    int G = gridDim.x;
    int L = ((int)blockIdx.x < T) ? (T - (int)blockIdx.x + G - 1) / G : 0;

    __syncthreads();

    int mRow = tid >> 5;           // 0..3; rows stride 4
    int c4   = tid & 31;

    for (int j = 0; j < L; j++) {
        long base = ((long)blockIdx.x + (long)j * G) * 64;

        // ---- stage tile (64 rows): LDG -> fp16 hi/lo -> STS; batch ids ----
#pragma unroll
        for (int r = 0; r < 16; r++) {
            int m = mRow + r * 4;
            long gi = base + m;
            float4 v = make_float4(0.f, 0.f, 0.f, 0.f);
            if (gi < N) v = __ldg((const float4*)(x + gi * 128 + c4 * 4));
            uint2 hp, lp; split4h(v, hp, lp);
            uint32_t off = m * A_STRIDE + c4 * 8;
            *(uint2*)(smem + SC_AH + off) = hp;
            *(uint2*)(smem + SC_AL + off) = lp;
        }
        if (tid < 64) {
            long gi = base + tid;
            gb[tid] = (gi < N) ? batch[gi] : 0;
        }
        __syncthreads();

        // ---- HMMA: each warp 16 rows, packed-B LDS.128 ----
        uint32_t aH = sbase + SC_AH + (wid * 16 + lrow) * A_STRIDE + lk;
        uint32_t aL = aH + A64_TILE_B;
        float acc[8][4];
#pragma unroll
        for (int nt = 0; nt < 8; nt++)
#pragma unroll
            for (int c = 0; c < 4; c++) acc[nt][c] = 0.f;

#pragma unroll
        for (int kc = 0; kc < 8; kc++) {
            uint32_t ah[4], al[4];
            ldmat4(ah, aH + kc * 32);
            ldmat4(al, aL + kc * 32);
            const uint4* bp = (const uint4*)(smem + SC_B + kc * BKC_STRIDE + lane * 80);
            uint4 q0 = bp[0], q1 = bp[1], q2 = bp[2], q3 = bp[3];
            hmma(acc[0], ah, q0.x, q0.y); hmma(acc[0], al, q0.x, q0.y);
            hmma(acc[1], ah, q0.z, q0.w); hmma(acc[1], al, q0.z, q0.w);
            hmma(acc[2], ah, q1.x, q1.y); hmma(acc[2], al, q1.x, q1.y);
            hmma(acc[3], ah, q1.z, q1.w); hmma(acc[3], al, q1.z, q1.w);
            hmma(acc[4], ah, q2.x, q2.y); hmma(acc[4], al, q2.x, q2.y);
            hmma(acc[5], ah, q2.z, q2.w); hmma(acc[5], al, q2.z, q2.w);
            hmma(acc[6], ah, q3.x, q3.y); hmma(acc[6], al, q3.x, q3.y);
            hmma(acc[7], ah, q3.z, q3.w); hmma(acc[7], al, q3.z, q3.w);
        }

        // ---- epilogue: e = exp(s); g_e, RED den; per-warp pooling ----
        int m0 = wid * 16 + g;
        int m1 = m0 + 8;
        long r0 = base + m0, r1 = base + m1;
        int bi0 = gb[m0], bi1 = gb[m1];
        {
            const float* t0 = g_t + (size_t)bi0 * 64;
            const float* t1 = g_t + (size_t)bi1 * 64;
            float s0 = 0.f, s1 = 0.f;
#pragma unroll
            for (int nt = 0; nt < 8; nt++) {
                int col = nt * 8 + 2 * t;
                float2 tv0 = *(const float2*)(t0 + col);
                float2 tv1 = *(const float2*)(t1 + col);
                float2 w = w2r[nt];
                s0 += fmaxf(acc[nt][0] + tv0.x, 0.f) * w.x
                    + fmaxf(acc[nt][1] + tv0.y, 0.f) * w.y;
                s1 += fmaxf(acc[nt][2] + tv1.x, 0.f) * w.x
                    + fmaxf(acc[nt][3] + tv1.y, 0.f) * w.y;
            }
            s0 += __shfl_xor_sync(0xffffffffu, s0, 1);
            s0 += __shfl_xor_sync(0xffffffffu, s0, 2);
            s1 += __shfl_xor_sync(0xffffffffu, s1, 1);
            s1 += __shfl_xor_sync(0xffffffffu, s1, 2);
            float e0 = (r0 < N) ? __expf(s0 + b2v) : 0.f;
            float e1 = (r1 < N) ? __expf(s1 + b2v) : 0.f;
            if (t == 0) {
                if (r0 < N) { g_e[r0] = e0; atomicAdd(g_den + bi0, e0); }
                if (r1 < N) { g_e[r1] = e1; atomicAdd(g_den + bi1, e1); }
            }

            // per-warp pooling: 16 rows x 4 feats/lane from smem (x ~ hi+lo)
            float a0 = 0.f, a1 = 0.f, a2 = 0.f, a3 = 0.f;
            int rowBase = wid * 16;
#pragma unroll
            for (int r = 0; r < 16; r++) {
                int row = rowBase + r;
                float er = (r < 8) ? __shfl_sync(0xffffffffu, e0, r * 4)
                                   : __shfl_sync(0xffffffffu, e1, (r - 8) * 4);
                uint2 h = *(uint2*)(smem + SC_AH + row * A_STRIDE + lane * 8);
                uint2 l = *(uint2*)(smem + SC_AL + row * A_STRIDE + lane * 8);
                float2 h0 = __half22float2(*(__half2*)&h.x);
                float2 h1 = __half22float2(*(__half2*)&h.y);
                float2 l0 = __half22float2(*(__half2*)&l.x);
                float2 l1 = __half22float2(*(__half2*)&l.y);
                a0 += er * (h0.x + l0.x);
                a1 += er * (h0.y + l0.y);
                a2 += er * (h1.x + l1.x);
                a3 += er * (h1.y + l1.y);
                int gcur = gb[row];
                if (r == 15 || gb[row + 1] != gcur) {
                    float* dst = g_num + (size_t)gcur * 128 + lane * 4;
                    atomicAdd(dst,     a0);
                    atomicAdd(dst + 1, a1);
                    atomicAdd(dst + 2, a2);
                    atomicAdd(dst + 3, a3);
                    a0 = a1 = a2 = a3 = 0.f;
                }
            }
        }
        __syncthreads();
    }
}

// ================= merged post-processing =================
__global__ void __launch_bounds__(256) post_kernel(
    const float* __restrict__ u, const int* __restrict__ batch,
    float* __restrict__ attn, int N, int B)
{
    int nX2 = B * 32;
    int stride = gridDim.x * blockDim.x;
    for (int i = blockIdx.x * blockDim.x + threadIdx.x; i < nX2; i += stride) {
        int g = i >> 5, q = i & 31;
        float den = g_den[g];
        float inv = (den > 0.f) ? 1.f / den : 0.f;
        float4 uv = *(const float4*)(u + (size_t)g * 128 + q * 4);
        float4 nv = *(const float4*)(g_num + (size_t)g * 128 + q * 4);
        nv.x *= inv; nv.y *= inv; nv.z *= inv; nv.w *= inv;
        *(float4*)(g_x2 + (size_t)g * 256 + q * 4)       = uv;
        *(float4*)(g_x2 + (size_t)g * 256 + 128 + q * 4) = nv;
    }
    for (int i = blockIdx.x * blockDim.x + threadIdx.x; i < N; i += stride) {
        attn[i] = g_e[i] / g_den[batch[i]];
    }
}

// ================= launch =================
extern "C" void kernel_launch(void* const* d_in, const int* in_sizes, int n_in,
                              void* d_out, int out_size)
{
    const float* x     = (const float*)d_in[0];
    const float* u     = (const float*)d_in[3];
    const int*   batch = (const int*)d_in[4];
    const float* W1    = (const float*)d_in[5];
    const float* b1    = (const float*)d_in[6];
    const float* W2    = (const float*)d_in[7];
    const float* b2    = (const float*)d_in[8];
    const float* Wg1   = (const float*)d_in[9];
    const float* bg1   = (const float*)d_in[10];
    const float* Wg2   = (const float*)d_in[11];
    const float* bg2   = (const float*)d_in[12];

    int N = in_sizes[0] / 128;
    int B = in_sizes[3] / 128;

    float* out  = (float*)d_out;
    float* attn = (float*)d_out + (size_t)B * 128;

    float *t_ptr, *x2_ptr, *h2_ptr;
    cudaGetSymbolAddress((void**)&t_ptr,  g_t);
    cudaGetSymbolAddress((void**)&x2_ptr, g_x2);
    cudaGetSymbolAddress((void**)&h2_ptr, g_h2);
    uint4 *pw1a_ptr, *pw1b_ptr, *pwg1_ptr, *pwg2_ptr;
    cudaGetSymbolAddress((void**)&pw1a_ptr, g_pw1a);
    cudaGetSymbolAddress((void**)&pw1b_ptr, g_pw1b);
    cudaGetSymbolAddress((void**)&pwg1_ptr, g_pwg1);
    cudaGetSymbolAddress((void**)&pwg2_ptr, g_pwg2);

    cudaFuncSetAttribute(hmma_gemm,
                         cudaFuncAttributeMaxDynamicSharedMemorySize, GB_TOTAL);
    cudaFuncSetAttribute(scores_pool_kernel,
                         cudaFuncAttributeMaxDynamicSharedMemorySize, SC_TOTAL);

    // 0) prepack weights + zero accumulators
    pack_weights<<<112, 256>>>(W1, Wg1, Wg2);
    zero_kernel<<<(B * 129 + 255) / 256, 256>>>(B);

    // 1) t[B,64] = u @ W1b + b1
    {
        dim3 grid(1, B / 128);
        hmma_gemm<<<grid, 256, GB_TOTAL>>>(u, pw1b_ptr, b1, t_ptr, B, 64, 128, 0);
    }

    // 2) fused scores + softmax-pool (64-row tiles, fp16 2-term, 4 CTAs/SM)
    {
        int T = (N + 63) / 64;
        int grid = T < 592 ? T : 592;
        scores_pool_kernel<<<grid, 128, SC_TOTAL>>>(x, batch, W2, b2, N);
    }

    // 3) merged post-processing (x2 build + attn)
    post_kernel<<<1184, 256>>>(u, batch, attn, N, B);

    // 4) global MLP via fp16-split HMMA (prepacked weights)
    {
        dim3 g3a(256 / 64, B / 128);
        hmma_gemm<<<g3a, 256, GB_TOTAL>>>(x2_ptr, pwg1_ptr, bg1, h2_ptr, B, 256, 256, 1);
        dim3 g3b(128 / 64, B / 128);
        hmma_gemm<<<g3b, 256, GB_TOTAL>>>(h2_ptr, pwg2_ptr, bg2, out, B, 128, 256, 0);
    }
}